// round 2
// baseline (speedup 1.0000x reference)
#include <cuda_runtime.h>

#define NROWS 32768
#define DIM   256
#define NC    8192

#define BM 64
#define BN 64
#define BK 32
#define AP 260   // A smem row pitch (floats), 260*4=1040B, 16B aligned
#define BP 68    // B smem row pitch (floats), 68*4=272B, 16B aligned

// ---------------- scratch (device globals; no allocations allowed) ----------
__device__ float g_sumz[NROWS];
__device__ float g_cnorm[NC];
__device__ int   g_idx[NROWS];
__device__ float g_count[NC];
__device__ float g_wsum[NC * DIM];
__device__ float g_loss;
__device__ float g_n;

// ---------------- zero scratch ----------------------------------------------
__global__ void k_zero() {
    int i = blockIdx.x * blockDim.x + threadIdx.x;
    int stride = gridDim.x * blockDim.x;
    for (int j = i; j < NC * DIM; j += stride) g_wsum[j] = 0.0f;
    if (i < NC) g_count[i] = 0.0f;
    if (i == 0) { g_loss = 0.0f; g_n = 0.0f; }
}

// ---------------- row sum of squares (strided lanes, mul then add — no FMA) -
__global__ void k_rownorm(const float* __restrict__ x, float* __restrict__ out, int rows) {
    int warp = (blockIdx.x * blockDim.x + threadIdx.x) >> 5;
    int lane = threadIdx.x & 31;
    if (warp >= rows) return;
    const float* row = x + (size_t)warp * DIM;
    float s = 0.0f;
#pragma unroll
    for (int m = 0; m < 8; m++) {
        float v = row[lane + 32 * m];
        s = __fadd_rn(s, __fmul_rn(v, v));
    }
#pragma unroll
    for (int o = 16; o > 0; o >>= 1)
        s = __fadd_rn(s, __shfl_down_sync(0xffffffffu, s, o));
    if (lane == 0) out[warp] = s;
}

// ---------------- distance GEMM + online argmin ------------------------------
// dists = fl(fl(sumz - 2*dot) + cnorm), dot accumulated with ordered-k fp32 FMA.
// Ties broken by lowest code index (matches jnp.argmin).
__global__ void k_argmin(const float* __restrict__ z, const float* __restrict__ cbw,
                         const float* __restrict__ sumz, const float* __restrict__ cnorm,
                         int* __restrict__ idx_out, float* __restrict__ idxf_out) {
    extern __shared__ float sm[];
    float* As = sm;               // [BM][AP] row-major (m, k), full K resident
    float* Bs = sm + BM * AP;     // [BK][BP] k-major (k, n)

    int t = threadIdx.x;
    int row0 = blockIdx.x * BM;

    // Load entire A tile (64 rows x 256 k) once: 4096 float4, 16 per thread
#pragma unroll
    for (int i = 0; i < 16; i++) {
        int p  = t + i * 256;
        int r  = p >> 6;
        int kq = p & 63;
        float4 v = *reinterpret_cast<const float4*>(z + (size_t)(row0 + r) * DIM + kq * 4);
        *reinterpret_cast<float4*>(As + r * AP + kq * 4) = v;
    }
    __syncthreads();

    int ty = t >> 4, tx = t & 15;
    int m0 = ty * 4, n0 = tx * 4;

    float szr[4];
#pragma unroll
    for (int i = 0; i < 4; i++) szr[i] = sumz[row0 + m0 + i];

    float bestv[4];
    int   besti[4];
#pragma unroll
    for (int i = 0; i < 4; i++) { bestv[i] = 3.4e38f; besti[i] = 0; }

    for (int cb0 = 0; cb0 < NC; cb0 += BN) {
        float acc[4][4];
#pragma unroll
        for (int i = 0; i < 4; i++)
#pragma unroll
            for (int j = 0; j < 4; j++) acc[i][j] = 0.0f;

        for (int kc = 0; kc < DIM; kc += BK) {
            // Load B tile (64 codes x 32 k), transpose into Bs[k][n]
#pragma unroll
            for (int q = 0; q < 2; q++) {
                int p  = t + q * 256;     // 0..511
                int r  = p >> 3;          // code 0..63
                int kq = p & 7;           // float4 within k-chunk
                float4 v = *reinterpret_cast<const float4*>(
                    cbw + (size_t)(cb0 + r) * DIM + kc + kq * 4);
                Bs[(kq * 4 + 0) * BP + r] = v.x;
                Bs[(kq * 4 + 1) * BP + r] = v.y;
                Bs[(kq * 4 + 2) * BP + r] = v.z;
                Bs[(kq * 4 + 3) * BP + r] = v.w;
            }
            __syncthreads();

#pragma unroll
            for (int k = 0; k < BK; k++) {
                float a0 = As[(m0 + 0) * AP + kc + k];
                float a1 = As[(m0 + 1) * AP + kc + k];
                float a2 = As[(m0 + 2) * AP + kc + k];
                float a3 = As[(m0 + 3) * AP + kc + k];
                float4 b = *reinterpret_cast<float4*>(Bs + k * BP + n0);
                acc[0][0] = __fmaf_rn(a0, b.x, acc[0][0]);
                acc[0][1] = __fmaf_rn(a0, b.y, acc[0][1]);
                acc[0][2] = __fmaf_rn(a0, b.z, acc[0][2]);
                acc[0][3] = __fmaf_rn(a0, b.w, acc[0][3]);
                acc[1][0] = __fmaf_rn(a1, b.x, acc[1][0]);
                acc[1][1] = __fmaf_rn(a1, b.y, acc[1][1]);
                acc[1][2] = __fmaf_rn(a1, b.z, acc[1][2]);
                acc[1][3] = __fmaf_rn(a1, b.w, acc[1][3]);
                acc[2][0] = __fmaf_rn(a2, b.x, acc[2][0]);
                acc[2][1] = __fmaf_rn(a2, b.y, acc[2][1]);
                acc[2][2] = __fmaf_rn(a2, b.z, acc[2][2]);
                acc[2][3] = __fmaf_rn(a2, b.w, acc[2][3]);
                acc[3][0] = __fmaf_rn(a3, b.x, acc[3][0]);
                acc[3][1] = __fmaf_rn(a3, b.y, acc[3][1]);
                acc[3][2] = __fmaf_rn(a3, b.z, acc[3][2]);
                acc[3][3] = __fmaf_rn(a3, b.w, acc[3][3]);
            }
            __syncthreads();
        }

        // Epilogue: d = fl(fl(sumz - 2*dot) + cnorm); strict < keeps lowest index
#pragma unroll
        for (int j = 0; j < 4; j++) {
            float cn = cnorm[cb0 + n0 + j];
#pragma unroll
            for (int i = 0; i < 4; i++) {
                float d = __fadd_rn(__fadd_rn(szr[i], -2.0f * acc[i][j]), cn);
                if (d < bestv[i]) { bestv[i] = d; besti[i] = cb0 + n0 + j; }
            }
        }
    }
    __syncthreads();

    // Cross-thread reduce (16 column-threads per row), tie -> lowest index
    float* rv = sm;                       // [64][16]
    int*   ri = (int*)(sm + 64 * 16);     // [64][16]
#pragma unroll
    for (int i = 0; i < 4; i++) {
        rv[(m0 + i) * 16 + tx] = bestv[i];
        ri[(m0 + i) * 16 + tx] = besti[i];
    }
    __syncthreads();
    if (t < 64) {
        float bv = rv[t * 16];
        int   bi = ri[t * 16];
#pragma unroll
        for (int x = 1; x < 16; x++) {
            float v  = rv[t * 16 + x];
            int   ii = ri[t * 16 + x];
            if (v < bv || (v == bv && ii < bi)) { bv = v; bi = ii; }
        }
        idx_out[row0 + t]  = bi;
        idxf_out[row0 + t] = (float)bi;
    }
}

// ---------------- scatter: counts, weight sums, loss partial, z_q ------------
__global__ void k_scatter(const float* __restrict__ z, const float* __restrict__ cbw,
                          const int* __restrict__ idx,
                          float* __restrict__ wsum, float* __restrict__ cnt,
                          float* __restrict__ lossacc, float* __restrict__ zq_out) {
    int warp = (blockIdx.x * blockDim.x + threadIdx.x) >> 5;
    int lane = threadIdx.x & 31;
    if (warp >= NROWS) return;
    int c = idx[warp];
    const float* zr = z   + (size_t)warp * DIM;
    const float* cr = cbw + (size_t)c    * DIM;
    float ls = 0.0f;
#pragma unroll
    for (int m = 0; m < 8; m++) {
        int d = lane + 32 * m;
        float zv = zr[d], cv = cr[d];
        atomicAdd(&wsum[c * DIM + d], zv);
        float diff = __fadd_rn(zv, -cv);             // fl(z - c)
        ls = __fadd_rn(ls, __fmul_rn(diff, diff));
        float st = __fadd_rn(cv, -zv);               // fl(c - z)
        zq_out[(size_t)warp * DIM + d] = __fadd_rn(zv, st);  // fl(z + fl(c - z))
    }
#pragma unroll
    for (int o = 16; o > 0; o >>= 1)
        ls = __fadd_rn(ls, __shfl_down_sync(0xffffffffu, ls, o));
    if (lane == 0) {
        atomicAdd(&cnt[c], 1.0f);
        atomicAdd(lossacc, ls);
    }
}

// ---------------- EMA count + n --------------------------------------------
__global__ void k_ema(const float* __restrict__ ema_count, const float* __restrict__ cnt,
                      float* __restrict__ out_count, float* __restrict__ n_acc) {
    int c = blockIdx.x * blockDim.x + threadIdx.x;
    float nec = 0.0f;
    if (c < NC) {
        nec = __fadd_rn(__fmul_rn(0.99f, ema_count[c]), __fmul_rn(0.01f, cnt[c]));
        out_count[c] = nec;
    }
    __shared__ float red[256];
    red[threadIdx.x] = nec;
    __syncthreads();
    for (int s = 128; s > 0; s >>= 1) {
        if (threadIdx.x < s) red[threadIdx.x] = __fadd_rn(red[threadIdx.x], red[threadIdx.x + s]);
        __syncthreads();
    }
    if (threadIdx.x == 0) atomicAdd(n_acc, red[0]);
}

// ---------------- new codebook + new ema weight ------------------------------
__global__ void k_codebook(const float* __restrict__ ema_weight, const float* __restrict__ wsum,
                           const float* __restrict__ out_count, const float* __restrict__ n_acc,
                           float* __restrict__ out_cb, float* __restrict__ out_ew) {
    size_t i = (size_t)blockIdx.x * 256 + threadIdx.x;
    if (i >= (size_t)NC * DIM) return;
    int c = (int)(i >> 8);
    float new_ew = __fadd_rn(__fmul_rn(0.99f, ema_weight[i]), __fmul_rn(0.01f, wsum[i]));
    out_ew[i] = new_ew;
    float n  = *n_acc;
    float a  = __fadd_rn(out_count[c], 1e-5f);
    float b  = __fadd_rn(n, 0.08192f);             // N_CODES * EPS in fp32
    float cs = __fmul_rn(__fdiv_rn(a, b), n);
    out_cb[i] = __fdiv_rn(new_ew, cs);
}

// ---------------- loss finalize ----------------------------------------------
__global__ void k_loss(const float* __restrict__ lossacc, float* __restrict__ out_loss) {
    float m = __fdiv_rn(*lossacc, 8388608.0f);     // mean over N*D (2^23, exact)
    *out_loss = __fmul_rn(0.25f, m);               // COMMITMENT_COST
}

// ---------------- launch ------------------------------------------------------
extern "C" void kernel_launch(void* const* d_in, const int* in_sizes, int n_in,
                              void* d_out, int out_size) {
    const float* z          = (const float*)d_in[0];
    const float* cbw        = (const float*)d_in[1];
    const float* ema_count  = (const float*)d_in[2];
    const float* ema_weight = (const float*)d_in[3];

    float* out      = (float*)d_out;
    float* out_zq   = out;                       // 8388608
    float* out_idx  = out + 8388608;             // 32768
    float* out_loss = out + 8421376;             // 1
    float* out_cb   = out + 8421377;             // 2097152
    float* out_cnt  = out + 10518529;            // 8192
    float* out_ew   = out + 10526721;            // 2097152

    float *p_sumz, *p_cnorm, *p_count, *p_wsum, *p_loss, *p_n;
    int* p_idx;
    cudaGetSymbolAddress((void**)&p_sumz,  g_sumz);
    cudaGetSymbolAddress((void**)&p_cnorm, g_cnorm);
    cudaGetSymbolAddress((void**)&p_idx,   g_idx);
    cudaGetSymbolAddress((void**)&p_count, g_count);
    cudaGetSymbolAddress((void**)&p_wsum,  g_wsum);
    cudaGetSymbolAddress((void**)&p_loss,  g_loss);
    cudaGetSymbolAddress((void**)&p_n,     g_n);

    const int smem_bytes = (BM * AP + BK * BP) * 4;   // 75264
    cudaFuncSetAttribute(k_argmin, cudaFuncAttributeMaxDynamicSharedMemorySize, smem_bytes);

    k_zero<<<2048, 256>>>();
    k_rownorm<<<4096, 256>>>(z,   p_sumz,  NROWS);
    k_rownorm<<<1024, 256>>>(cbw, p_cnorm, NC);
    k_argmin<<<NROWS / BM, 256, smem_bytes>>>(z, cbw, p_sumz, p_cnorm, p_idx, out_idx);
    k_scatter<<<4096, 256>>>(z, cbw, p_idx, p_wsum, p_count, p_loss, out_zq);
    k_ema<<<32, 256>>>(ema_count, p_count, out_cnt, p_n);
    k_codebook<<<8192, 256>>>(ema_weight, p_wsum, out_cnt, p_n, out_cb, out_ew);
    k_loss<<<1, 1>>>(p_loss, out_loss);
}

// round 4
// speedup vs baseline: 2.9518x; 2.9518x over previous
#include <cuda_runtime.h>
#include <cuda_bf16.h>
#include <cstdint>

#define NROWS 32768
#define DIM   256
#define NC    8192
#define MARGIN 8e-4f
#define PITCH 264                       // bf16 elems per smem row (+16B pad)
#define SMEM_TOTAL (2 * 128 * PITCH * 2) // 135168 B

// ---------------- scratch ----------------------------------------------------
__device__ float g_sumz[NROWS];
__device__ float g_cnorm[NC];
__device__ int   g_idx[NROWS];
__device__ float g_count[NC];
__device__ float g_wsum[NC * DIM];
__device__ float g_loss;
__device__ float g_n;
__device__ int   g_pmin[NROWS];                    // float bits, atomicMin (positive floats)
__device__ float g_dists[(size_t)NROWS * NC];      // 1 GB approx dists [row][code]
__device__ __nv_bfloat16 g_zb[NROWS * DIM];
__device__ __nv_bfloat16 g_cb[NC * DIM];

// ---------------- helpers -----------------------------------------------------
__device__ __forceinline__ uint32_t smem_u32(const void* p) {
    uint32_t a;
    asm("{ .reg .u64 t; cvta.to.shared.u64 t, %1; cvt.u32.u64 %0, t; }" : "=r"(a) : "l"(p));
    return a;
}
__device__ __forceinline__ void ldsm4(uint32_t& r0, uint32_t& r1, uint32_t& r2, uint32_t& r3, uint32_t addr) {
    asm volatile("ldmatrix.sync.aligned.m8n8.x4.shared.b16 {%0,%1,%2,%3}, [%4];"
                 : "=r"(r0), "=r"(r1), "=r"(r2), "=r"(r3) : "r"(addr));
}
__device__ __forceinline__ void mma16816(float* c, uint32_t a0, uint32_t a1, uint32_t a2, uint32_t a3,
                                         uint32_t b0, uint32_t b1) {
    asm volatile("mma.sync.aligned.m16n8k16.row.col.f32.bf16.bf16.f32 "
                 "{%0,%1,%2,%3}, {%4,%5,%6,%7}, {%8,%9}, {%0,%1,%2,%3};"
                 : "+f"(c[0]), "+f"(c[1]), "+f"(c[2]), "+f"(c[3])
                 : "r"(a0), "r"(a1), "r"(a2), "r"(a3), "r"(b0), "r"(b1));
}

// ---------------- zero scratch ------------------------------------------------
__global__ void k_zero() {
    int i = blockIdx.x * blockDim.x + threadIdx.x;
    int stride = gridDim.x * blockDim.x;
    for (int j = i; j < NC * DIM; j += stride) g_wsum[j] = 0.0f;
    for (int j = i; j < NROWS; j += stride) g_pmin[j] = 0x7F800000;  // +inf
    if (i < NC) g_count[i] = 0.0f;
    if (i == 0) { g_loss = 0.0f; g_n = 0.0f; }
}

// ---------------- prep: row norms + bf16 round --------------------------------
__global__ void k_prep(const float* __restrict__ x, __nv_bfloat16* __restrict__ ob,
                       float* __restrict__ norm, int rows) {
    int w = (blockIdx.x * blockDim.x + threadIdx.x) >> 5;
    int lane = threadIdx.x & 31;
    if (w >= rows) return;
    const float* row = x + (size_t)w * DIM;
    float s = 0.0f;
#pragma unroll
    for (int m = 0; m < 8; m++) { float v = row[lane + 32*m]; s = __fadd_rn(s, __fmul_rn(v, v)); }
#pragma unroll
    for (int o = 16; o > 0; o >>= 1) s = __fadd_rn(s, __shfl_down_sync(0xffffffffu, s, o));
    if (lane == 0) norm[w] = s;

    __align__(16) __nv_bfloat16 b0[8];
#pragma unroll
    for (int q = 0; q < 8; q++) b0[q] = __float2bfloat16_rn(row[lane*8 + q]);
    *reinterpret_cast<uint4*>(ob + (size_t)w*DIM + lane*8) = *reinterpret_cast<uint4*>(b0);
}

// ---------------- HMMA distance GEMM + approx min ------------------------------
// grid (64 code-chunks [x fastest -> L2 reuse of A], 256 row-chunks), 256 thr.
__global__ void __launch_bounds__(256, 1) k_mma(
    const __nv_bfloat16* __restrict__ zb, const __nv_bfloat16* __restrict__ cb,
    const float* __restrict__ sumz, const float* __restrict__ cnorm,
    float* __restrict__ dists, int* __restrict__ pmin)
{
    extern __shared__ __nv_bfloat16 smem[];
    __nv_bfloat16* As = smem;                 // [128][PITCH]
    __nv_bfloat16* Bs = smem + 128 * PITCH;   // [128][PITCH]
    const int tid = threadIdx.x;
    const int row0 = blockIdx.y * 128;
    const int col0 = blockIdx.x * 128;

    // cooperative load: A rows row0..+127, B codes col0..+127, full K=256
    {
        const uint4* Ag = reinterpret_cast<const uint4*>(zb + (size_t)row0 * DIM);
        const uint4* Bg = reinterpret_cast<const uint4*>(cb + (size_t)col0 * DIM);
#pragma unroll
        for (int i = 0; i < 16; i++) {
            int u = tid + i * 256;            // 0..4095
            int r = u >> 5, ch = u & 31;      // row, 8-bf16 chunk
            reinterpret_cast<uint4*>(As + r * PITCH + ch * 8)[0] = Ag[u];
            reinterpret_cast<uint4*>(Bs + r * PITCH + ch * 8)[0] = Bg[u];
        }
    }
    __syncthreads();

    const int wid = tid >> 5, lane = tid & 31;
    const int wm = wid & 3;                   // 4 warps in m: 32 rows each
    const int wn = wid >> 2;                  // 2 warps in n: 64 cols each

    const uint32_t sbA = smem_u32(As), sbB = smem_u32(Bs);
    // ldmatrix lane address pattern: lanes 0-15 rows +0..15 col k; 16-31 rows +0..15 col k+8
    const uint32_t aBase = sbA + (uint32_t)(((wm*32 + (lane & 15)) * PITCH + (lane >> 4) * 8) * 2);
    const uint32_t bBase = sbB + (uint32_t)(((wn*64 + (lane & 15)) * PITCH + (lane >> 4) * 8) * 2);

    float c[2][8][4];
#pragma unroll
    for (int mt = 0; mt < 2; mt++)
#pragma unroll
        for (int nt = 0; nt < 8; nt++)
#pragma unroll
            for (int q = 0; q < 4; q++) c[mt][nt][q] = 0.0f;

#pragma unroll
    for (int k = 0; k < DIM; k += 16) {
        uint32_t a[2][4], b[4][4];
#pragma unroll
        for (int mt = 0; mt < 2; mt++)
            ldsm4(a[mt][0], a[mt][1], a[mt][2], a[mt][3], aBase + (uint32_t)((mt*16*PITCH + k) * 2));
#pragma unroll
        for (int ng = 0; ng < 4; ng++)
            ldsm4(b[ng][0], b[ng][1], b[ng][2], b[ng][3], bBase + (uint32_t)((ng*16*PITCH + k) * 2));
#pragma unroll
        for (int mt = 0; mt < 2; mt++)
#pragma unroll
            for (int ng = 0; ng < 4; ng++) {
                mma16816(c[mt][2*ng + 0], a[mt][0], a[mt][1], a[mt][2], a[mt][3], b[ng][0], b[ng][2]);
                mma16816(c[mt][2*ng + 1], a[mt][0], a[mt][1], a[mt][2], a[mt][3], b[ng][1], b[ng][3]);
            }
    }

    // epilogue: d = fl(fl(sumz - 2*dot) + cnorm); write dists; per-row approx min
    const int g = lane >> 2, t = lane & 3;
#pragma unroll
    for (int mt = 0; mt < 2; mt++) {
        int r_lo = row0 + wm*32 + mt*16 + g;
        int r_hi = r_lo + 8;
        float s_lo = sumz[r_lo], s_hi = sumz[r_hi];
        float mn_lo = 3.4e38f, mn_hi = 3.4e38f;
#pragma unroll
        for (int nt = 0; nt < 8; nt++) {
            int col = col0 + wn*64 + nt*8 + t*2;
            float2 cn = *reinterpret_cast<const float2*>(cnorm + col);
            float d00 = __fadd_rn(__fadd_rn(s_lo, -2.0f * c[mt][nt][0]), cn.x);
            float d01 = __fadd_rn(__fadd_rn(s_lo, -2.0f * c[mt][nt][1]), cn.y);
            float d10 = __fadd_rn(__fadd_rn(s_hi, -2.0f * c[mt][nt][2]), cn.x);
            float d11 = __fadd_rn(__fadd_rn(s_hi, -2.0f * c[mt][nt][3]), cn.y);
            mn_lo = fminf(mn_lo, fminf(d00, d01));
            mn_hi = fminf(mn_hi, fminf(d10, d11));
            *reinterpret_cast<float2*>(dists + (size_t)r_lo * NC + col) = make_float2(d00, d01);
            *reinterpret_cast<float2*>(dists + (size_t)r_hi * NC + col) = make_float2(d10, d11);
        }
        // reduce across the 4 lanes of the quad (same row, different t)
#pragma unroll
        for (int o = 1; o < 4; o <<= 1) {
            mn_lo = fminf(mn_lo, __shfl_xor_sync(0xffffffffu, mn_lo, o));
            mn_hi = fminf(mn_hi, __shfl_xor_sync(0xffffffffu, mn_hi, o));
        }
        if (t == 0) {
            atomicMin(&pmin[r_lo], __float_as_int(mn_lo));
            atomicMin(&pmin[r_hi], __float_as_int(mn_hi));
        }
    }
}

// ---------------- exact candidate refinement ----------------------------------
__global__ void k_select(const float* __restrict__ z, const float* __restrict__ cbw,
                         const float* __restrict__ sumz, const float* __restrict__ cnorm,
                         const int* __restrict__ pmin, const float* __restrict__ dists,
                         int* __restrict__ idx_out, float* __restrict__ idxf_out) {
    int w = (blockIdx.x * blockDim.x + threadIdx.x) >> 5;
    int lane = threadIdx.x & 31;
    if (w >= NROWS) return;
    const float* drow = dists + (size_t)w * NC;
    float thr = __int_as_float(pmin[w]) + MARGIN;
    float bv = 3.4e38f; int bi = NC;
    const float* zr = z + (size_t)w * DIM;
    float sz = sumz[w];
#pragma unroll 4
    for (int cc = lane; cc < NC; cc += 32) {
        float d = drow[cc];
        if (d <= thr) {
            const float* cr = cbw + (size_t)cc * DIM;
            float acc = 0.0f;
            for (int k2 = 0; k2 < DIM; k2++) acc = __fmaf_rn(zr[k2], cr[k2], acc);
            float de = __fadd_rn(__fadd_rn(sz, -2.0f * acc), cnorm[cc]);
            if (de < bv || (de == bv && cc < bi)) { bv = de; bi = cc; }
        }
    }
#pragma unroll
    for (int o = 16; o > 0; o >>= 1) {
        float ov = __shfl_down_sync(0xffffffffu, bv, o);
        int   oi = __shfl_down_sync(0xffffffffu, bi, o);
        if (ov < bv || (ov == bv && oi < bi)) { bv = ov; bi = oi; }
    }
    if (lane == 0) { idx_out[w] = bi; idxf_out[w] = (float)bi; }
}

// ---------------- scatter: counts, weight sums, loss partial, z_q -------------
__global__ void k_scatter(const float* __restrict__ z, const float* __restrict__ cbw,
                          const int* __restrict__ idx,
                          float* __restrict__ wsum, float* __restrict__ cnt,
                          float* __restrict__ lossacc, float* __restrict__ zq_out) {
    int warp = (blockIdx.x * blockDim.x + threadIdx.x) >> 5;
    int lane = threadIdx.x & 31;
    if (warp >= NROWS) return;
    int c = idx[warp];
    const float* zr = z   + (size_t)warp * DIM;
    const float* cr = cbw + (size_t)c    * DIM;
    float ls = 0.0f;
#pragma unroll
    for (int m = 0; m < 8; m++) {
        int d = lane + 32*m;
        float zv = zr[d], cv = cr[d];
        atomicAdd(&wsum[c * DIM + d], zv);
        float diff = __fadd_rn(zv, -cv);
        ls = __fadd_rn(ls, __fmul_rn(diff, diff));
        float st = __fadd_rn(cv, -zv);
        zq_out[(size_t)warp * DIM + d] = __fadd_rn(zv, st);
    }
#pragma unroll
    for (int o = 16; o > 0; o >>= 1) ls = __fadd_rn(ls, __shfl_down_sync(0xffffffffu, ls, o));
    if (lane == 0) { atomicAdd(&cnt[c], 1.0f); atomicAdd(lossacc, ls); }
}

// ---------------- EMA count + n ----------------------------------------------
__global__ void k_ema(const float* __restrict__ ema_count, const float* __restrict__ cnt,
                      float* __restrict__ out_count, float* __restrict__ n_acc) {
    int c = blockIdx.x * blockDim.x + threadIdx.x;
    float nec = 0.0f;
    if (c < NC) {
        nec = __fadd_rn(__fmul_rn(0.99f, ema_count[c]), __fmul_rn(0.01f, cnt[c]));
        out_count[c] = nec;
    }
    __shared__ float red[256];
    red[threadIdx.x] = nec;
    __syncthreads();
    for (int s = 128; s > 0; s >>= 1) {
        if (threadIdx.x < s) red[threadIdx.x] = __fadd_rn(red[threadIdx.x], red[threadIdx.x + s]);
        __syncthreads();
    }
    if (threadIdx.x == 0) atomicAdd(n_acc, red[0]);
}

// ---------------- new codebook + new ema weight -------------------------------
__global__ void k_codebook(const float* __restrict__ ema_weight, const float* __restrict__ wsum,
                           const float* __restrict__ out_count, const float* __restrict__ n_acc,
                           float* __restrict__ out_cb, float* __restrict__ out_ew) {
    size_t i = (size_t)blockIdx.x * 256 + threadIdx.x;
    if (i >= (size_t)NC * DIM) return;
    int c = (int)(i >> 8);
    float new_ew = __fadd_rn(__fmul_rn(0.99f, ema_weight[i]), __fmul_rn(0.01f, wsum[i]));
    out_ew[i] = new_ew;
    float n  = *n_acc;
    float a  = __fadd_rn(out_count[c], 1e-5f);
    float b  = __fadd_rn(n, 0.08192f);
    float cs = __fmul_rn(__fdiv_rn(a, b), n);
    out_cb[i] = __fdiv_rn(new_ew, cs);
}

__global__ void k_loss(const float* __restrict__ lossacc, float* __restrict__ out_loss) {
    float m = __fdiv_rn(*lossacc, 8388608.0f);
    *out_loss = __fmul_rn(0.25f, m);
}

// ---------------- launch ------------------------------------------------------
extern "C" void kernel_launch(void* const* d_in, const int* in_sizes, int n_in,
                              void* d_out, int out_size) {
    const float* z          = (const float*)d_in[0];
    const float* cbw        = (const float*)d_in[1];
    const float* ema_count  = (const float*)d_in[2];
    const float* ema_weight = (const float*)d_in[3];

    float* out      = (float*)d_out;
    float* out_zq   = out;
    float* out_idx  = out + 8388608;
    float* out_loss = out + 8421376;
    float* out_cb   = out + 8421377;
    float* out_cnt  = out + 10518529;
    float* out_ew   = out + 10526721;

    float *p_sumz, *p_cnorm, *p_count, *p_wsum, *p_loss, *p_n, *p_dists;
    int *p_idx, *p_pmin;
    __nv_bfloat16 *p_zb, *p_cb;
    cudaGetSymbolAddress((void**)&p_sumz,  g_sumz);
    cudaGetSymbolAddress((void**)&p_cnorm, g_cnorm);
    cudaGetSymbolAddress((void**)&p_idx,   g_idx);
    cudaGetSymbolAddress((void**)&p_count, g_count);
    cudaGetSymbolAddress((void**)&p_wsum,  g_wsum);
    cudaGetSymbolAddress((void**)&p_loss,  g_loss);
    cudaGetSymbolAddress((void**)&p_n,     g_n);
    cudaGetSymbolAddress((void**)&p_pmin,  g_pmin);
    cudaGetSymbolAddress((void**)&p_dists, g_dists);
    cudaGetSymbolAddress((void**)&p_zb,    g_zb);
    cudaGetSymbolAddress((void**)&p_cb,    g_cb);

    cudaFuncSetAttribute(k_mma, cudaFuncAttributeMaxDynamicSharedMemorySize, SMEM_TOTAL);

    k_zero<<<2048, 256>>>();
    k_prep<<<4096, 256>>>(z,   p_zb, p_sumz,  NROWS);
    k_prep<<<1024, 256>>>(cbw, p_cb, p_cnorm, NC);
    dim3 grid(NC / 128, NROWS / 128);   // x = code chunk (fastest) for L2 reuse
    k_mma<<<grid, 256, SMEM_TOTAL>>>(p_zb, p_cb, p_sumz, p_cnorm, p_dists, p_pmin);
    k_select<<<4096, 256>>>(z, cbw, p_sumz, p_cnorm, p_pmin, p_dists, p_idx, out_idx);
    k_scatter<<<4096, 256>>>(z, cbw, p_idx, p_wsum, p_count, p_loss, out_zq);
    k_ema<<<32, 256>>>(ema_count, p_count, out_cnt, p_n);
    k_codebook<<<8192, 256>>>(ema_weight, p_wsum, out_cnt, p_n, out_cb, out_ew);
    k_loss<<<1, 1>>>(p_loss, out_loss);
}